// round 9
// baseline (speedup 1.0000x reference)
#include <cuda_runtime.h>
#include <cuda_bf16.h>
#include <cstdint>

#define BATCH 8
#define EDGES 16384
#define C0 128
#define C1 256
#define OUTC 256
#define KD0 (6 * C0)   // 768  (x5 column folded into weights)
#define KD1 (6 * C1)   // 1536
#define NEG 0.01f
#define BN_EPS_ 1e-5f

// ---------------- static device scratch ----------------
__device__ __nv_bfloat16 g_Abf[(size_t)BATCH * EDGES * 2 * KD1];  // [M][hi(K)|lo(K)]
__device__ __nv_bfloat16 g_W0pp[OUTC * 2 * KD0];                  // [o][hi(K)|lo(K)]
__device__ __nv_bfloat16 g_W1pp[OUTC * 2 * KD1];
__device__ float g_xt[(size_t)BATCH * EDGES * C0];
__device__ float g_at[(size_t)BATCH * EDGES * C1];   // lrelu(h0) transposed (pre-BN)
__device__ float g_h0[(size_t)BATCH * OUTC * EDGES];
__device__ float g_sum1[OUTC], g_sum2[OUTC], g_scale[OUTC], g_shift[OUTC];

// ---------------- helpers ----------------
__device__ __forceinline__ uint32_t smem_u32(const void* p) {
    uint32_t a;
    asm("{ .reg .u64 t; cvta.to.shared.u64 t, %1; cvt.u32.u64 %0, t; }" : "=r"(a) : "l"(p));
    return a;
}
__device__ __forceinline__ uint32_t sw64(uint32_t x) { return x ^ ((x >> 3) & 0x30); }
__device__ __forceinline__ void cpa16(uint32_t s, const void* g) {
    asm volatile("cp.async.cg.shared.global [%0], [%1], 16;" :: "r"(s), "l"(g));
}
__device__ __forceinline__ void cpa_commit() { asm volatile("cp.async.commit_group;"); }
__device__ __forceinline__ void cpa_wait2() { asm volatile("cp.async.wait_group 2;"); }

__device__ __forceinline__ void ldsm4(uint32_t* r, uint32_t addr) {
    asm volatile("ldmatrix.sync.aligned.m8n8.x4.shared.b16 {%0,%1,%2,%3}, [%4];"
                 : "=r"(r[0]), "=r"(r[1]), "=r"(r[2]), "=r"(r[3]) : "r"(addr));
}
__device__ __forceinline__ void mma16816(float* d, const uint32_t* a, uint32_t b0, uint32_t b1) {
    asm volatile(
        "mma.sync.aligned.m16n8k16.row.col.f32.bf16.bf16.f32 "
        "{%0,%1,%2,%3}, {%4,%5,%6,%7}, {%8,%9}, {%0,%1,%2,%3};"
        : "+f"(d[0]), "+f"(d[1]), "+f"(d[2]), "+f"(d[3])
        : "r"(a[0]), "r"(a[1]), "r"(a[2]), "r"(a[3]), "r"(b0), "r"(b1));
}

// ---------------- W prep: fold x5 col into x1,x2; drop x5. [o][hi(K6)|lo(K6)] ----------------
template <int WHICH>
__global__ void prep_wpp(const float* __restrict__ W) {
    constexpr int C = (WHICH == 0) ? C0 : C1;
    constexpr int K6 = 6 * C;
    __nv_bfloat16* Wpp = (WHICH == 0) ? g_W0pp : g_W1pp;
    if (WHICH == 0 && blockIdx.x == 0 && threadIdx.x < 256) {
        g_sum1[threadIdx.x] = 0.f;
        g_sum2[threadIdx.x] = 0.f;
    }
    int i = blockIdx.x * blockDim.x + threadIdx.x;
    if (i < OUTC * K6) {
        int kp = i % K6, o = i / K6;
        int c = kp / 6, jp = kp % 6;
        int jorig = (jp == 5) ? 6 : jp;
        float v = W[(size_t)o * (7 * C) + c * 7 + jorig];
        if (jp == 1 || jp == 2) v += W[(size_t)o * (7 * C) + c * 7 + 5];  // fold x5
        __nv_bfloat16 h = __float2bfloat16(v);
        __nv_bfloat16 l = __float2bfloat16(v - __bfloat162float(h));
        Wpp[(size_t)o * 2 * K6 + kp] = h;
        Wpp[(size_t)o * 2 * K6 + K6 + kp] = l;
    }
}

// ---------------- transpose x [B][C0][E] -> g_xt [B][E][C0] ----------------
__global__ void transpose_x(const float* __restrict__ x) {
    __shared__ float tile[32][33];
    int b = blockIdx.z;
    int e0 = blockIdx.x * 32, c0 = blockIdx.y * 32;
    int tx = threadIdx.x, ty = threadIdx.y;
#pragma unroll
    for (int i = 0; i < 32; i += 8)
        tile[ty + i][tx] = x[((size_t)b * C0 + (c0 + ty + i)) * EDGES + e0 + tx];
    __syncthreads();
#pragma unroll
    for (int i = 0; i < 32; i += 8)
        g_xt[((size_t)b * EDGES + (e0 + ty + i)) * C0 + c0 + tx] = tile[tx][ty + i];
}

// ---------------- gather + 6-feature build + bf16 hi/lo split ----------------
template <int STAGE>
__global__ __launch_bounds__(256, 1) void gather_bf16(const int* __restrict__ gem) {
    constexpr int C = (STAGE == 0) ? C0 : C1;
    constexpr int K = 6 * C;
    constexpr int PITCH = 2 * K;
    constexpr int GPE = C / 8;
    const float* __restrict__ src = (STAGE == 0) ? g_xt : g_at;

    int gidx = blockIdx.x * blockDim.x + threadIdx.x;
    int m = gidx / GPE;
    int c = (gidx % GPE) * 8;
    size_t bE = (size_t)(m / EDGES) * EDGES;
    const int* gp = gem + (size_t)m * 4;
    int n0 = gp[0], n1 = gp[1], n2 = gp[2], n3 = gp[3];

    const float4* p0 = (const float4*)(src + (size_t)m * C + c);
    const float4* p1 = (const float4*)(src + (bE + n0) * (size_t)C + c);
    const float4* p2 = (const float4*)(src + (bE + n1) * (size_t)C + c);
    const float4* p3 = (const float4*)(src + (bE + n2) * (size_t)C + c);
    const float4* p4 = (const float4*)(src + (bE + n3) * (size_t)C + c);

    float f0[8], f1[8], f2[8], f3[8], f4[8];
    {
        float4 a = p0[0], b = p0[1];
        f0[0]=a.x; f0[1]=a.y; f0[2]=a.z; f0[3]=a.w; f0[4]=b.x; f0[5]=b.y; f0[6]=b.z; f0[7]=b.w;
        a = p1[0]; b = p1[1];
        f1[0]=a.x; f1[1]=a.y; f1[2]=a.z; f1[3]=a.w; f1[4]=b.x; f1[5]=b.y; f1[6]=b.z; f1[7]=b.w;
        a = p2[0]; b = p2[1];
        f2[0]=a.x; f2[1]=a.y; f2[2]=a.z; f2[3]=a.w; f2[4]=b.x; f2[5]=b.y; f2[6]=b.z; f2[7]=b.w;
        a = p3[0]; b = p3[1];
        f3[0]=a.x; f3[1]=a.y; f3[2]=a.z; f3[3]=a.w; f3[4]=b.x; f3[5]=b.y; f3[6]=b.z; f3[7]=b.w;
        a = p4[0]; b = p4[1];
        f4[0]=a.x; f4[1]=a.y; f4[2]=a.z; f4[3]=a.w; f4[4]=b.x; f4[5]=b.y; f4[6]=b.z; f4[7]=b.w;
    }

    if (STAGE == 1) {
        float4 s0 = *(const float4*)(g_scale + c), s1v = *(const float4*)(g_scale + c + 4);
        float4 h0 = *(const float4*)(g_shift + c), h1v = *(const float4*)(g_shift + c + 4);
        float sc[8] = {s0.x, s0.y, s0.z, s0.w, s1v.x, s1v.y, s1v.z, s1v.w};
        float sh[8] = {h0.x, h0.y, h0.z, h0.w, h1v.x, h1v.y, h1v.z, h1v.w};
#pragma unroll
        for (int k = 0; k < 8; k++) {
            f0[k] = fmaf(sc[k], f0[k], sh[k]);
            f1[k] = fmaf(sc[k], f1[k], sh[k]);
            f2[k] = fmaf(sc[k], f2[k], sh[k]);
            f3[k] = fmaf(sc[k], f3[k], sh[k]);
            f4[k] = fmaf(sc[k], f4[k], sh[k]);
        }
    }

    float feat[48];
#pragma unroll
    for (int cl = 0; cl < 8; cl++) {
        float a = f1[cl], b = f2[cl], cc = f3[cl], d = f4[cl];
        float x1 = a + cc, x2 = b + d, x5 = x1 + x2, avg = 0.25f * x5;
        float d1 = a - avg, d2 = b - avg, d3 = cc - avg, d4 = d - avg;
        feat[cl * 6 + 0] = f0[cl];
        feat[cl * 6 + 1] = x1;
        feat[cl * 6 + 2] = x2;
        feat[cl * 6 + 3] = fabsf(a - cc);
        feat[cl * 6 + 4] = fabsf(b - d);
        feat[cl * 6 + 5] = d1 * d1 + d2 * d2 + d3 * d3 + d4 * d4;
    }

    uint32_t hw[24], lw[24];
#pragma unroll
    for (int q = 0; q < 24; q++) {
        float v0 = feat[2 * q], v1 = feat[2 * q + 1];
        __nv_bfloat16 h0 = __float2bfloat16(v0), h1 = __float2bfloat16(v1);
        float l0 = v0 - __bfloat162float(h0), l1 = v1 - __bfloat162float(h1);
        __nv_bfloat16 g0 = __float2bfloat16(l0), g1 = __float2bfloat16(l1);
        hw[q] = (uint32_t)__bfloat16_as_ushort(h0) | ((uint32_t)__bfloat16_as_ushort(h1) << 16);
        lw[q] = (uint32_t)__bfloat16_as_ushort(g0) | ((uint32_t)__bfloat16_as_ushort(g1) << 16);
    }
    uint4* dh = (uint4*)(g_Abf + (size_t)m * PITCH + c * 6);
    uint4* dl = (uint4*)(g_Abf + (size_t)m * PITCH + K + c * 6);
#pragma unroll
    for (int q = 0; q < 6; q++) {
        dh[q] = make_uint4(hw[4 * q], hw[4 * q + 1], hw[4 * q + 2], hw[4 * q + 3]);
        dl[q] = make_uint4(lw[4 * q], lw[4 * q + 1], lw[4 * q + 2], lw[4 * q + 3]);
    }
}

// ---------------- mma.sync GEMM: 128x256 CTA, 8 warps, warp tile 64x64 ----------------
#define AH_OFF 0
#define AL_OFF 8192
#define WH_OFF 16384
#define WL_OFF 32768
#define STG 49152
#define GEMM_SMEM 196608  // 4 stages; epilogue reuses 256x129 f32 buf

template <int MODE>
__global__ __launch_bounds__(256, 1) void gemm_mma(float* __restrict__ outp) {
    constexpr int K = MODE ? KD1 : KD0;
    constexpr int T = K / 32;
    constexpr int PITCH = 2 * K;
    const __nv_bfloat16* __restrict__ Wpp = MODE ? g_W1pp : g_W0pp;

    extern __shared__ __align__(1024) char smem[];
    uint32_t sb = smem_u32(smem);
    const int tid = threadIdx.x, wid = tid >> 5, lane = tid & 31;
    const int wm = wid & 1, wn = wid >> 1;          // 2 M-groups x 4 N-groups, 64x64 tiles
    const size_t m0 = (size_t)blockIdx.x * 128;

    float acc[4][8][4];
#pragma unroll
    for (int i = 0; i < 4; i++)
#pragma unroll
        for (int j = 0; j < 8; j++)
#pragma unroll
            for (int k = 0; k < 4; k++) acc[i][j][k] = 0.f;

    const int lr = tid >> 2;   // 0..63
    const int lc = tid & 3;    // 16B chunk

    auto load_stage = [&](int slot, int t) {
        const __nv_bfloat16* Ag = g_Abf + m0 * (size_t)PITCH + t * 32;
        const __nv_bfloat16* Wg = Wpp + t * 32;
        uint32_t st = sb + slot * STG;
        // A: 128 rows (2 per thread) hi+lo
#pragma unroll
        for (int i = 0; i < 2; i++) {
            int r = lr + i * 64;
            const __nv_bfloat16* as = Ag + (size_t)r * PITCH + lc * 8;
            uint32_t d = sw64(r * 64 + lc * 16);
            cpa16(st + AH_OFF + d, as);
            cpa16(st + AL_OFF + d, as + K);
        }
        // W: 256 rows (4 per thread) hi+lo
#pragma unroll
        for (int i = 0; i < 4; i++) {
            int r = lr + i * 64;
            const __nv_bfloat16* ws = Wg + (size_t)r * PITCH + lc * 8;
            uint32_t wd = sw64(r * 64 + lc * 16);
            cpa16(st + WH_OFF + wd, ws);
            cpa16(st + WL_OFF + wd, ws + K);
        }
    };

    load_stage(0, 0); cpa_commit();
    load_stage(1, 1); cpa_commit();
    load_stage(2, 2); cpa_commit();

    const int lrow = lane & 15;
    const int lcol = (lane >> 4) * 16;

    for (int t = 0; t < T; t++) {
        int s = t & 3;
        cpa_wait2();
        __syncthreads();
        if (t + 3 < T) load_stage((t + 3) & 3, t + 3);
        cpa_commit();
        uint32_t st = sb + s * STG;
#pragma unroll
        for (int ks = 0; ks < 2; ks++) {
            int ko = ks * 32;
            uint32_t ah[4][4], al[4][4], bb[4][4];
#pragma unroll
            for (int mi = 0; mi < 4; mi++)
                ldsm4(ah[mi], st + AH_OFF + sw64((wm * 64 + mi * 16 + lrow) * 64 + ko + lcol));
#pragma unroll
            for (int nj = 0; nj < 4; nj++)
                ldsm4(bb[nj], st + WH_OFF + sw64((wn * 64 + nj * 16 + lrow) * 64 + ko + lcol));
            // pass 1: ah . wh  (32 independent mmas)
#pragma unroll
            for (int mi = 0; mi < 4; mi++)
#pragma unroll
                for (int nj = 0; nj < 4; nj++) {
                    mma16816(acc[mi][2 * nj], ah[mi], bb[nj][0], bb[nj][2]);
                    mma16816(acc[mi][2 * nj + 1], ah[mi], bb[nj][1], bb[nj][3]);
                }
            // pass 2: al . wh
#pragma unroll
            for (int mi = 0; mi < 4; mi++)
                ldsm4(al[mi], st + AL_OFF + sw64((wm * 64 + mi * 16 + lrow) * 64 + ko + lcol));
#pragma unroll
            for (int mi = 0; mi < 4; mi++)
#pragma unroll
                for (int nj = 0; nj < 4; nj++) {
                    mma16816(acc[mi][2 * nj], al[mi], bb[nj][0], bb[nj][2]);
                    mma16816(acc[mi][2 * nj + 1], al[mi], bb[nj][1], bb[nj][3]);
                }
            // pass 3: ah . wl (reload bb with wl)
#pragma unroll
            for (int nj = 0; nj < 4; nj++)
                ldsm4(bb[nj], st + WL_OFF + sw64((wn * 64 + nj * 16 + lrow) * 64 + ko + lcol));
#pragma unroll
            for (int mi = 0; mi < 4; mi++)
#pragma unroll
                for (int nj = 0; nj < 4; nj++) {
                    mma16816(acc[mi][2 * nj], ah[mi], bb[nj][0], bb[nj][2]);
                    mma16816(acc[mi][2 * nj + 1], ah[mi], bb[nj][1], bb[nj][3]);
                }
        }
    }

    // ---------------- epilogue: CTA transpose buffer [256 o][129] ----------------
    __syncthreads();
    float* buf = (float*)smem;  // [256][129]
    {
        int q = lane >> 2, idq = lane & 3;
#pragma unroll
        for (int mi = 0; mi < 4; mi++)
#pragma unroll
            for (int p = 0; p < 8; p++) {
                int e = wm * 64 + mi * 16 + q;
                int o = wn * 64 + p * 8 + idq * 2;
                buf[o * 129 + e] = acc[mi][p][0];
                buf[(o + 1) * 129 + e] = acc[mi][p][1];
                buf[o * 129 + e + 8] = acc[mi][p][2];
                buf[(o + 1) * 129 + e + 8] = acc[mi][p][3];
            }
    }
    __syncthreads();

    const int b = blockIdx.x >> 7;
    const int e0 = (blockIdx.x & 127) * 128;

    // row pass: each thread owns channel o = tid
    {
        int o = tid;
        const float* src = buf + o * 129;
        size_t gbase = ((size_t)b * OUTC + o) * EDGES + e0;
        if (MODE == 0) {
            float s1 = 0.f, s2 = 0.f;
#pragma unroll 4
            for (int i = 0; i < 32; i++) {
                float v0 = src[4 * i], v1 = src[4 * i + 1], v2 = src[4 * i + 2], v3 = src[4 * i + 3];
                *(float4*)(g_h0 + gbase + 4 * i) = make_float4(v0, v1, v2, v3);
                float a;
                a = v0 > 0.f ? v0 : NEG * v0; s1 += a; s2 += a * a;
                a = v1 > 0.f ? v1 : NEG * v1; s1 += a; s2 += a * a;
                a = v2 > 0.f ? v2 : NEG * v2; s1 += a; s2 += a * a;
                a = v3 > 0.f ? v3 : NEG * v3; s1 += a; s2 += a * a;
            }
            atomicAdd(&g_sum1[o], s1);
            atomicAdd(&g_sum2[o], s2);
        } else {
#pragma unroll 4
            for (int i = 0; i < 32; i++) {
                float4 hres = *(const float4*)(g_h0 + gbase + 4 * i);
                float v0 = src[4 * i] + hres.x, v1 = src[4 * i + 1] + hres.y;
                float v2 = src[4 * i + 2] + hres.z, v3 = src[4 * i + 3] + hres.w;
                v0 = v0 > 0.f ? v0 : NEG * v0;
                v1 = v1 > 0.f ? v1 : NEG * v1;
                v2 = v2 > 0.f ? v2 : NEG * v2;
                v3 = v3 > 0.f ? v3 : NEG * v3;
                *(float4*)(outp + gbase + 4 * i) = make_float4(v0, v1, v2, v3);
            }
        }
    }

    if (MODE == 0) {
        // column pass: e-major (g_at = lrelu(h0)), coalesced across lanes
        int eo = tid >> 5, j = tid & 31;
#pragma unroll 1
        for (int it = 0; it < 16; it++) {
            int e = it * 8 + eo;
            float* dst = g_at + ((size_t)b * EDGES + e0 + e) * C1;
#pragma unroll
            for (int k = 0; k < 8; k++) {
                int o = j + 32 * k;
                float v = buf[o * 129 + e];
                dst[o] = v > 0.f ? v : NEG * v;
            }
        }
    }
}

// ---------------- BN finalize ----------------
__global__ void bn_finalize(const float* __restrict__ gamma, const float* __restrict__ beta) {
    int o = threadIdx.x;
    float n = (float)((size_t)BATCH * EDGES);
    float mean = g_sum1[o] / n;
    float var = g_sum2[o] / n - mean * mean;
    float sc = gamma[o] * rsqrtf(var + BN_EPS_);
    g_scale[o] = sc;
    g_shift[o] = beta[o] - mean * sc;
}

// ---------------- launch ----------------
extern "C" void kernel_launch(void* const* d_in, const int* in_sizes, int n_in,
                              void* d_out, int out_size) {
    (void)in_sizes; (void)n_in; (void)out_size;
    const float* x     = (const float*)d_in[0];
    const int*   gem   = (const int*)d_in[1];
    const float* W0    = (const float*)d_in[2];
    const float* W1    = (const float*)d_in[3];
    const float* gamma = (const float*)d_in[4];
    const float* beta  = (const float*)d_in[5];
    float* out = (float*)d_out;

    cudaFuncSetAttribute(gemm_mma<0>, cudaFuncAttributeMaxDynamicSharedMemorySize, GEMM_SMEM);
    cudaFuncSetAttribute(gemm_mma<1>, cudaFuncAttributeMaxDynamicSharedMemorySize, GEMM_SMEM);

    // order chosen so the 4th launch (ncu sample target) is gemm0
    transpose_x<<<dim3(EDGES / 32, C0 / 32, BATCH), dim3(32, 8)>>>(x);
    prep_wpp<0><<<(OUTC * KD0 + 255) / 256, 256>>>(W0);   // also zeroes BN sums
    gather_bf16<0><<<BATCH * EDGES * (C0 / 8) / 256, 256>>>(gem);
    gemm_mma<0><<<BATCH * EDGES / 128, 256, GEMM_SMEM>>>(nullptr);  // 4th launch

    bn_finalize<<<1, 256>>>(gamma, beta);
    prep_wpp<1><<<(OUTC * KD1 + 255) / 256, 256>>>(W1);

    gather_bf16<1><<<BATCH * EDGES * (C1 / 8) / 256, 256>>>(gem);
    gemm_mma<1><<<BATCH * EDGES / 128, 256, GEMM_SMEM>>>(out);
}

// round 10
// speedup vs baseline: 1.2957x; 1.2957x over previous
#include <cuda_runtime.h>
#include <cuda_fp16.h>
#include <cstdint>

#define BATCH 8
#define EDGES 16384
#define C0 128
#define C1 256
#define OUTC 256
#define KD0 (6 * C0)   // 768  (x5 column folded into weights)
#define KD1 (6 * C1)   // 1536
#define NEG 0.01f
#define BN_EPS_ 1e-5f

// ---------------- static device scratch ----------------
__device__ __half g_Ahf[(size_t)BATCH * EDGES * 2 * KD1];  // [M][hi(K)|lo(K)] fp16
__device__ __half g_W0h[OUTC * KD0];                       // [o][K] single fp16
__device__ __half g_W1h[OUTC * KD1];
__device__ float g_xt[(size_t)BATCH * EDGES * C0];
__device__ float g_at[(size_t)BATCH * EDGES * C1];   // lrelu(h0) transposed (pre-BN)
__device__ float g_h0[(size_t)BATCH * OUTC * EDGES];
__device__ float g_sum1[OUTC], g_sum2[OUTC], g_scale[OUTC], g_shift[OUTC];

// ---------------- helpers ----------------
__device__ __forceinline__ uint32_t smem_u32(const void* p) {
    uint32_t a;
    asm("{ .reg .u64 t; cvta.to.shared.u64 t, %1; cvt.u32.u64 %0, t; }" : "=r"(a) : "l"(p));
    return a;
}
__device__ __forceinline__ uint32_t sw64(uint32_t x) { return x ^ ((x >> 3) & 0x30); }
__device__ __forceinline__ void cpa16(uint32_t s, const void* g) {
    asm volatile("cp.async.cg.shared.global [%0], [%1], 16;" :: "r"(s), "l"(g));
}
__device__ __forceinline__ void cpa_commit() { asm volatile("cp.async.commit_group;"); }
__device__ __forceinline__ void cpa_wait2() { asm volatile("cp.async.wait_group 2;"); }

__device__ __forceinline__ void ldsm4(uint32_t* r, uint32_t addr) {
    asm volatile("ldmatrix.sync.aligned.m8n8.x4.shared.b16 {%0,%1,%2,%3}, [%4];"
                 : "=r"(r[0]), "=r"(r[1]), "=r"(r[2]), "=r"(r[3]) : "r"(addr));
}
__device__ __forceinline__ void mma16816(float* d, const uint32_t* a, uint32_t b0, uint32_t b1) {
    asm volatile(
        "mma.sync.aligned.m16n8k16.row.col.f32.f16.f16.f32 "
        "{%0,%1,%2,%3}, {%4,%5,%6,%7}, {%8,%9}, {%0,%1,%2,%3};"
        : "+f"(d[0]), "+f"(d[1]), "+f"(d[2]), "+f"(d[3])
        : "r"(a[0]), "r"(a[1]), "r"(a[2]), "r"(a[3]), "r"(b0), "r"(b1));
}

// ---------------- W prep: fold x5 col into x1,x2; drop x5. [o][K6] single fp16 ----------------
// feature order per channel: 0:f0 1:x1 2:x2 3:x3 4:x4 5:x6
template <int WHICH>
__global__ void prep_wh(const float* __restrict__ W) {
    constexpr int C = (WHICH == 0) ? C0 : C1;
    constexpr int K6 = 6 * C;
    __half* Wh = (WHICH == 0) ? g_W0h : g_W1h;
    if (WHICH == 0 && blockIdx.x == 0 && threadIdx.x < 256) {
        g_sum1[threadIdx.x] = 0.f;
        g_sum2[threadIdx.x] = 0.f;
    }
    int i = blockIdx.x * blockDim.x + threadIdx.x;
    if (i < OUTC * K6) {
        int kp = i % K6, o = i / K6;
        int c = kp / 6, jp = kp % 6;
        int jorig = (jp == 5) ? 6 : jp;
        float v = W[(size_t)o * (7 * C) + c * 7 + jorig];
        if (jp == 1 || jp == 2) v += W[(size_t)o * (7 * C) + c * 7 + 5];  // fold x5
        Wh[(size_t)o * K6 + kp] = __float2half(v);
    }
}

// ---------------- transpose x [B][C0][E] -> g_xt [B][E][C0] ----------------
__global__ void transpose_x(const float* __restrict__ x) {
    __shared__ float tile[32][33];
    int b = blockIdx.z;
    int e0 = blockIdx.x * 32, c0 = blockIdx.y * 32;
    int tx = threadIdx.x, ty = threadIdx.y;
#pragma unroll
    for (int i = 0; i < 32; i += 8)
        tile[ty + i][tx] = x[((size_t)b * C0 + (c0 + ty + i)) * EDGES + e0 + tx];
    __syncthreads();
#pragma unroll
    for (int i = 0; i < 32; i += 8)
        g_xt[((size_t)b * EDGES + (e0 + ty + i)) * C0 + c0 + tx] = tile[tx][ty + i];
}

// ---------------- gather + 6-feature build + fp16 hi/lo split ----------------
template <int STAGE>
__global__ __launch_bounds__(256, 1) void gather_hf(const int* __restrict__ gem) {
    constexpr int C = (STAGE == 0) ? C0 : C1;
    constexpr int K = 6 * C;
    constexpr int PITCH = 2 * K;
    constexpr int GPE = C / 8;
    const float* __restrict__ src = (STAGE == 0) ? g_xt : g_at;

    int gidx = blockIdx.x * blockDim.x + threadIdx.x;
    int m = gidx / GPE;
    int c = (gidx % GPE) * 8;
    size_t bE = (size_t)(m / EDGES) * EDGES;
    const int* gp = gem + (size_t)m * 4;
    int n0 = gp[0], n1 = gp[1], n2 = gp[2], n3 = gp[3];

    const float4* p0 = (const float4*)(src + (size_t)m * C + c);
    const float4* p1 = (const float4*)(src + (bE + n0) * (size_t)C + c);
    const float4* p2 = (const float4*)(src + (bE + n1) * (size_t)C + c);
    const float4* p3 = (const float4*)(src + (bE + n2) * (size_t)C + c);
    const float4* p4 = (const float4*)(src + (bE + n3) * (size_t)C + c);

    float f0[8], f1[8], f2[8], f3[8], f4[8];
    {
        float4 a = p0[0], b = p0[1];
        f0[0]=a.x; f0[1]=a.y; f0[2]=a.z; f0[3]=a.w; f0[4]=b.x; f0[5]=b.y; f0[6]=b.z; f0[7]=b.w;
        a = p1[0]; b = p1[1];
        f1[0]=a.x; f1[1]=a.y; f1[2]=a.z; f1[3]=a.w; f1[4]=b.x; f1[5]=b.y; f1[6]=b.z; f1[7]=b.w;
        a = p2[0]; b = p2[1];
        f2[0]=a.x; f2[1]=a.y; f2[2]=a.z; f2[3]=a.w; f2[4]=b.x; f2[5]=b.y; f2[6]=b.z; f2[7]=b.w;
        a = p3[0]; b = p3[1];
        f3[0]=a.x; f3[1]=a.y; f3[2]=a.z; f3[3]=a.w; f3[4]=b.x; f3[5]=b.y; f3[6]=b.z; f3[7]=b.w;
        a = p4[0]; b = p4[1];
        f4[0]=a.x; f4[1]=a.y; f4[2]=a.z; f4[3]=a.w; f4[4]=b.x; f4[5]=b.y; f4[6]=b.z; f4[7]=b.w;
    }

    if (STAGE == 1) {
        float4 s0 = *(const float4*)(g_scale + c), s1v = *(const float4*)(g_scale + c + 4);
        float4 h0 = *(const float4*)(g_shift + c), h1v = *(const float4*)(g_shift + c + 4);
        float sc[8] = {s0.x, s0.y, s0.z, s0.w, s1v.x, s1v.y, s1v.z, s1v.w};
        float sh[8] = {h0.x, h0.y, h0.z, h0.w, h1v.x, h1v.y, h1v.z, h1v.w};
#pragma unroll
        for (int k = 0; k < 8; k++) {
            f0[k] = fmaf(sc[k], f0[k], sh[k]);
            f1[k] = fmaf(sc[k], f1[k], sh[k]);
            f2[k] = fmaf(sc[k], f2[k], sh[k]);
            f3[k] = fmaf(sc[k], f3[k], sh[k]);
            f4[k] = fmaf(sc[k], f4[k], sh[k]);
        }
    }

    float feat[48];
#pragma unroll
    for (int cl = 0; cl < 8; cl++) {
        float a = f1[cl], b = f2[cl], cc = f3[cl], d = f4[cl];
        float x1 = a + cc, x2 = b + d, x5 = x1 + x2, avg = 0.25f * x5;
        float d1 = a - avg, d2 = b - avg, d3 = cc - avg, d4 = d - avg;
        feat[cl * 6 + 0] = f0[cl];
        feat[cl * 6 + 1] = x1;
        feat[cl * 6 + 2] = x2;
        feat[cl * 6 + 3] = fabsf(a - cc);
        feat[cl * 6 + 4] = fabsf(b - d);
        feat[cl * 6 + 5] = d1 * d1 + d2 * d2 + d3 * d3 + d4 * d4;
    }

    uint32_t hw[24], lw[24];
#pragma unroll
    for (int q = 0; q < 24; q++) {
        float v0 = feat[2 * q], v1 = feat[2 * q + 1];
        __half h0 = __float2half(v0), h1 = __float2half(v1);
        float l0 = v0 - __half2float(h0), l1 = v1 - __half2float(h1);
        __half g0 = __float2half(l0), g1 = __float2half(l1);
        hw[q] = (uint32_t)__half_as_ushort(h0) | ((uint32_t)__half_as_ushort(h1) << 16);
        lw[q] = (uint32_t)__half_as_ushort(g0) | ((uint32_t)__half_as_ushort(g1) << 16);
    }
    uint4* dh = (uint4*)(g_Ahf + (size_t)m * PITCH + c * 6);
    uint4* dl = (uint4*)(g_Ahf + (size_t)m * PITCH + K + c * 6);
#pragma unroll
    for (int q = 0; q < 6; q++) {
        dh[q] = make_uint4(hw[4 * q], hw[4 * q + 1], hw[4 * q + 2], hw[4 * q + 3]);
        dl[q] = make_uint4(lw[4 * q], lw[4 * q + 1], lw[4 * q + 2], lw[4 * q + 3]);
    }
}

// ---------------- mma.sync GEMM: D[128,256] per CTA, fp16 2-term split ----------------
#define AH_OFF 0
#define AL_OFF 8192
#define WH_OFF 16384
#define STG 32768
#define GEMM_SMEM 135168  // max(4 stages = 128KB, epilogue 256*129*4 + 2KB = 131KB)

template <int MODE>
__global__ __launch_bounds__(512, 1) void gemm_mma(float* __restrict__ outp) {
    constexpr int K = MODE ? KD1 : KD0;
    constexpr int T = K / 32;
    constexpr int PITCH = 2 * K;
    const __half* __restrict__ Wh = MODE ? g_W1h : g_W0h;

    extern __shared__ __align__(1024) char smem[];
    uint32_t sb = smem_u32(smem);
    const int tid = threadIdx.x, wid = tid >> 5, lane = tid & 31;
    const int wm = wid & 3, wn = wid >> 2;
    const size_t m0 = (size_t)blockIdx.x * 128;

    float acc[2][8][4];
#pragma unroll
    for (int i = 0; i < 2; i++)
#pragma unroll
        for (int j = 0; j < 8; j++)
#pragma unroll
            for (int k = 0; k < 4; k++) acc[i][j][k] = 0.f;

    const int lr = tid >> 2;   // 0..127
    const int lc = tid & 3;    // 16B chunk within 64B row
    const uint32_t adst = sw64(lr * 64 + lc * 16);

    auto load_stage = [&](int slot, int t) {
        const __half* Ag = g_Ahf + m0 * (size_t)PITCH + t * 32;
        const __half* Wg = Wh + t * 32;
        uint32_t st = sb + slot * STG;
        const __half* as = Ag + (size_t)lr * PITCH + lc * 8;
        cpa16(st + AH_OFF + adst, as);
        cpa16(st + AL_OFF + adst, as + K);
#pragma unroll
        for (int i = 0; i < 2; i++) {
            int r = lr + i * 128;
            const __half* ws = Wg + (size_t)r * K + lc * 8;
            cpa16(st + WH_OFF + sw64(r * 64 + lc * 16), ws);
        }
    };

    load_stage(0, 0); cpa_commit();
    load_stage(1, 1); cpa_commit();
    load_stage(2, 2); cpa_commit();

    const int lrow = lane & 15;
    const int lcol = (lane >> 4) * 16;

    for (int t = 0; t < T; t++) {
        int s = t & 3;
        cpa_wait2();
        __syncthreads();
        if (t + 3 < T) load_stage((t + 3) & 3, t + 3);
        cpa_commit();
        uint32_t st = sb + s * STG;
#pragma unroll
        for (int ks = 0; ks < 2; ks++) {
            int ko = ks * 32;
            uint32_t ah[2][4], al[2][4], bb[4][4];
#pragma unroll
            for (int mi = 0; mi < 2; mi++) {
                uint32_t ao = sw64((wm * 32 + mi * 16 + lrow) * 64 + ko + lcol);
                ldsm4(ah[mi], st + AH_OFF + ao);
                ldsm4(al[mi], st + AL_OFF + ao);
            }
#pragma unroll
            for (int nj = 0; nj < 4; nj++)
                ldsm4(bb[nj], st + WH_OFF + sw64((wn * 64 + nj * 16 + lrow) * 64 + ko + lcol));
            // pass 1: ah . wh
#pragma unroll
            for (int mi = 0; mi < 2; mi++)
#pragma unroll
                for (int nj = 0; nj < 4; nj++) {
                    mma16816(acc[mi][2 * nj], ah[mi], bb[nj][0], bb[nj][2]);
                    mma16816(acc[mi][2 * nj + 1], ah[mi], bb[nj][1], bb[nj][3]);
                }
            // pass 2: al . wh
#pragma unroll
            for (int mi = 0; mi < 2; mi++)
#pragma unroll
                for (int nj = 0; nj < 4; nj++) {
                    mma16816(acc[mi][2 * nj], al[mi], bb[nj][0], bb[nj][2]);
                    mma16816(acc[mi][2 * nj + 1], al[mi], bb[nj][1], bb[nj][3]);
                }
        }
    }

    // ---------------- epilogue: CTA transpose buffer ----------------
    __syncthreads();
    float* buf = (float*)smem;                 // [256][129]
    float* bs = (float*)smem + 256 * 129;      // 512 floats
    {
        int q = lane >> 2, idq = lane & 3;
#pragma unroll
        for (int mi = 0; mi < 2; mi++)
#pragma unroll
            for (int p = 0; p < 8; p++) {
                int e = wm * 32 + mi * 16 + q;
                int o = wn * 64 + p * 8 + idq * 2;
                buf[o * 129 + e] = acc[mi][p][0];
                buf[(o + 1) * 129 + e] = acc[mi][p][1];
                buf[o * 129 + e + 8] = acc[mi][p][2];
                buf[(o + 1) * 129 + e + 8] = acc[mi][p][3];
            }
    }
    if (MODE == 0) bs[tid] = 0.f;
    __syncthreads();

    const int b = blockIdx.x >> 7;
    const int e0 = (blockIdx.x & 127) * 128;

    // row pass: o-major (g_h0 / out), coalesced float4 stores
    {
        int o = tid >> 1, h = (tid & 1) * 64;
        const float* src = buf + o * 129 + h;
        size_t gbase = ((size_t)b * OUTC + o) * EDGES + e0 + h;
        if (MODE == 0) {
            float s1 = 0.f, s2 = 0.f;
#pragma unroll 4
            for (int i = 0; i < 16; i++) {
                float v0 = src[4 * i], v1 = src[4 * i + 1], v2 = src[4 * i + 2], v3 = src[4 * i + 3];
                *(float4*)(g_h0 + gbase + 4 * i) = make_float4(v0, v1, v2, v3);
                float a;
                a = v0 > 0.f ? v0 : NEG * v0; s1 += a; s2 += a * a;
                a = v1 > 0.f ? v1 : NEG * v1; s1 += a; s2 += a * a;
                a = v2 > 0.f ? v2 : NEG * v2; s1 += a; s2 += a * a;
                a = v3 > 0.f ? v3 : NEG * v3; s1 += a; s2 += a * a;
            }
            atomicAdd(&bs[o], s1);
            atomicAdd(&bs[256 + o], s2);
        } else {
#pragma unroll 4
            for (int i = 0; i < 16; i++) {
                float4 hres = *(const float4*)(g_h0 + gbase + 4 * i);
                float v0 = src[4 * i] + hres.x, v1 = src[4 * i + 1] + hres.y;
                float v2 = src[4 * i + 2] + hres.z, v3 = src[4 * i + 3] + hres.w;
                v0 = v0 > 0.f ? v0 : NEG * v0;
                v1 = v1 > 0.f ? v1 : NEG * v1;
                v2 = v2 > 0.f ? v2 : NEG * v2;
                v3 = v3 > 0.f ? v3 : NEG * v3;
                *(float4*)(outp + gbase + 4 * i) = make_float4(v0, v1, v2, v3);
            }
        }
    }

    if (MODE == 0) {
        // column pass: e-major (g_at = lrelu(h0)), conflict-free strided reads
        {
            int eo = tid >> 6, j = tid & 63;
#pragma unroll 1
            for (int it = 0; it < 16; it++) {
                int e = it * 8 + eo;
                float* dst = g_at + ((size_t)b * EDGES + e0 + e) * C1;
#pragma unroll
                for (int k = 0; k < 4; k++) {
                    int o = j + 64 * k;
                    float v = buf[o * 129 + e];
                    dst[o] = v > 0.f ? v : NEG * v;
                }
            }
        }
        __syncthreads();
        if (tid < 256) {
            atomicAdd(&g_sum1[tid], bs[tid]);
            atomicAdd(&g_sum2[tid], bs[tid + 256]);
        }
    }
}

// ---------------- BN finalize ----------------
__global__ void bn_finalize(const float* __restrict__ gamma, const float* __restrict__ beta) {
    int o = threadIdx.x;
    float n = (float)((size_t)BATCH * EDGES);
    float mean = g_sum1[o] / n;
    float var = g_sum2[o] / n - mean * mean;
    float sc = gamma[o] * rsqrtf(var + BN_EPS_);
    g_scale[o] = sc;
    g_shift[o] = beta[o] - mean * sc;
}

// ---------------- launch ----------------
extern "C" void kernel_launch(void* const* d_in, const int* in_sizes, int n_in,
                              void* d_out, int out_size) {
    (void)in_sizes; (void)n_in; (void)out_size;
    const float* x     = (const float*)d_in[0];
    const int*   gem   = (const int*)d_in[1];
    const float* W0    = (const float*)d_in[2];
    const float* W1    = (const float*)d_in[3];
    const float* gamma = (const float*)d_in[4];
    const float* beta  = (const float*)d_in[5];
    float* out = (float*)d_out;

    cudaFuncSetAttribute(gemm_mma<0>, cudaFuncAttributeMaxDynamicSharedMemorySize, GEMM_SMEM);
    cudaFuncSetAttribute(gemm_mma<1>, cudaFuncAttributeMaxDynamicSharedMemorySize, GEMM_SMEM);

    // order chosen so the 4th launch (ncu sample target) is gemm0
    transpose_x<<<dim3(EDGES / 32, C0 / 32, BATCH), dim3(32, 8)>>>(x);
    prep_wh<0><<<(OUTC * KD0 + 255) / 256, 256>>>(W0);   // also zeroes BN sums
    gather_hf<0><<<BATCH * EDGES * (C0 / 8) / 256, 256>>>(gem);
    gemm_mma<0><<<BATCH * EDGES / 128, 512, GEMM_SMEM>>>(nullptr);  // 4th launch

    bn_finalize<<<1, 256>>>(gamma, beta);
    prep_wh<1><<<(OUTC * KD1 + 255) / 256, 256>>>(W1);

    gather_hf<1><<<BATCH * EDGES * (C1 / 8) / 256, 256>>>(gem);
    gemm_mma<1><<<BATCH * EDGES / 128, 512, GEMM_SMEM>>>(out);
}